// round 5
// baseline (speedup 1.0000x reference)
#include <cuda_runtime.h>

#define NN 50000
#define EE 800000
#define TEg (EE + NN)          // edges + self loops
#define NEG_SLOPE 0.2f

// -------- static device scratch (no allocations allowed) --------
__device__ float g_h[NN * 64];     // GEMM output (h of current layer)
__device__ float g_act[NN * 64];   // layer-1 activated output
__device__ float g_as[NN];
__device__ float g_ad[NN];
__device__ int   g_cnt[NN];
__device__ int   g_rowptr[NN + 1];
__device__ int   g_cursor[NN];
__device__ int   g_srcidx[TEg];
__device__ int   g_bsums[128];
__device__ int   g_boff[128];
__device__ int   g_is64;           // 1 if edge_index buffer is int64, 0 if int32

// ---------------- dtype detection ----------------
// If int64: odd 32-bit words (high halves) are all 0 (indices in [0,50000)).
// If int32: odd words are node indices, overwhelmingly nonzero.
__global__ void k_detect(const int* __restrict__ ei32) {
    __shared__ int sm[256];
    int t = threadIdx.x;
    int acc = 0;
    // scan odd words of first 32768 pairs (64K int32 words, safe in both interps)
    for (int i = t; i < 32768; i += 256)
        acc |= ei32[2 * i + 1];
    sm[t] = acc;
    __syncthreads();
    for (int off = 128; off; off >>= 1) {
        if (t < off) sm[t] |= sm[t + off];
        __syncthreads();
    }
    if (t == 0) g_is64 = (sm[0] == 0) ? 1 : 0;
}

__device__ __forceinline__ int load_idx(const void* ei, long long pos) {
    if (g_is64) return (int)((const long long*)ei)[pos];
    return ((const int*)ei)[pos];
}

// ---------------- CSR build ----------------
__global__ void k_init() {
    int i = blockIdx.x * blockDim.x + threadIdx.x;
    if (i < NN) g_cnt[i] = 0;
}

__global__ void k_hist(const void* __restrict__ ei) {
    int i = blockIdx.x * blockDim.x + threadIdx.x;
    if (i >= TEg) return;
    int d = (i < EE) ? load_idx(ei, (long long)EE + i) : (i - EE);
    if (d >= 0 && d < NN) atomicAdd(&g_cnt[d], 1);
}

__global__ void k_scan1() {
    __shared__ int sm[512];
    int t = threadIdx.x;
    int i = blockIdx.x * 512 + t;
    int v = (i < NN) ? g_cnt[i] : 0;
    sm[t] = v;
    __syncthreads();
    for (int off = 1; off < 512; off <<= 1) {
        int add = (t >= off) ? sm[t - off] : 0;
        __syncthreads();
        sm[t] += add;
        __syncthreads();
    }
    if (i < NN) g_rowptr[i + 1] = sm[t];
    if (t == 511) g_bsums[blockIdx.x] = sm[511];
}

__global__ void k_scan2(int nblocks) {
    __shared__ int sm[128];
    int t = threadIdx.x;
    int v = (t < nblocks) ? g_bsums[t] : 0;
    sm[t] = v;
    __syncthreads();
    for (int off = 1; off < 128; off <<= 1) {
        int add = (t >= off) ? sm[t - off] : 0;
        __syncthreads();
        sm[t] += add;
        __syncthreads();
    }
    g_boff[t] = sm[t] - v;  // exclusive prefix of block sums
}

__global__ void k_scan3() {
    int i = blockIdx.x * blockDim.x + threadIdx.x;
    if (i == 0) { g_rowptr[0] = 0; g_cursor[0] = 0; }
    if (i < NN) {
        int v = g_rowptr[i + 1] + g_boff[i >> 9];
        g_rowptr[i + 1] = v;
        if (i + 1 < NN) g_cursor[i + 1] = v;
    }
}

__global__ void k_scatter(const void* __restrict__ ei) {
    int i = blockIdx.x * blockDim.x + threadIdx.x;
    if (i >= TEg) return;
    int s, d;
    if (i < EE) {
        s = load_idx(ei, i);
        d = load_idx(ei, (long long)EE + i);
    } else {
        s = i - EE; d = s;
    }
    if (d < 0 || d >= NN || s < 0 || s >= NN) return;
    int pos = atomicAdd(&g_cursor[d], 1);
    if (pos >= 0 && pos < TEg) g_srcidx[pos] = s;
}

// ---------------- tiled GEMM (all-scalar memory ops) ----------------
// H[N,64] = X[N,FIN] @ W[FIN,64]. Block tile 64x64, 256 threads, thread tile 4x4.
template <int FIN, bool USE_ACT>
__global__ __launch_bounds__(256)
void k_gemm(const float* __restrict__ Xext, const float* __restrict__ W) {
    __shared__ float Xs[64][33];
    __shared__ float Ws[32][65];

    const float* X = USE_ACT ? (const float*)g_act : Xext;

    int tid = threadIdx.x;
    int tx = tid & 15;          // column group (4 cols)
    int ty = tid >> 4;          // row group (4 rows)
    int row0 = blockIdx.x * 64;

    float acc[4][4] = {};

    for (int k0 = 0; k0 < FIN; k0 += 32) {
        #pragma unroll
        for (int l = 0; l < 8; ++l) {
            int idx = l * 256 + tid;
            int r = idx >> 5, c = idx & 31;
            int row = row0 + r;
            float v = 0.f;
            if (row < NN) v = X[(size_t)row * FIN + k0 + c];
            Xs[r][c] = v;
        }
        #pragma unroll
        for (int l = 0; l < 8; ++l) {
            int idx = l * 256 + tid;
            int k = idx >> 6, c = idx & 63;
            Ws[k][c] = W[(size_t)(k0 + k) * 64 + c];
        }
        __syncthreads();

        #pragma unroll
        for (int kk = 0; kk < 32; ++kk) {
            float xv[4], wv[4];
            #pragma unroll
            for (int r = 0; r < 4; ++r) xv[r] = Xs[ty * 4 + r][kk];
            #pragma unroll
            for (int c = 0; c < 4; ++c) wv[c] = Ws[kk][tx * 4 + c];
            #pragma unroll
            for (int r = 0; r < 4; ++r)
                #pragma unroll
                for (int c = 0; c < 4; ++c)
                    acc[r][c] = fmaf(xv[r], wv[c], acc[r][c]);
        }
        __syncthreads();
    }

    #pragma unroll
    for (int r = 0; r < 4; ++r) {
        int row = row0 + ty * 4 + r;
        if (row < NN) {
            #pragma unroll
            for (int c = 0; c < 4; ++c)
                g_h[(size_t)row * 64 + tx * 4 + c] = acc[r][c];
        }
    }
}

// ---------------- attention projections ----------------
__global__ __launch_bounds__(256)
void k_proj(const float* __restrict__ a_src, const float* __restrict__ a_dst) {
    int w = (blockIdx.x * blockDim.x + threadIdx.x) >> 5;
    int lane = threadIdx.x & 31;
    if (w >= NN) return;

    float h0 = g_h[(size_t)w * 64 + lane];
    float h1 = g_h[(size_t)w * 64 + 32 + lane];
    float s = h0 * a_src[lane] + h1 * a_src[lane + 32];
    float d = h0 * a_dst[lane] + h1 * a_dst[lane + 32];
    #pragma unroll
    for (int off = 16; off; off >>= 1) {
        s += __shfl_xor_sync(0xffffffffu, s, off);
        d += __shfl_xor_sync(0xffffffffu, d, off);
    }
    if (lane == 0) { g_as[w] = s; g_ad[w] = d; }
}

// ---------------- segment softmax + aggregation ----------------
template <bool WRITE_ACT>
__global__ __launch_bounds__(256)
void k_agg(const float* __restrict__ bias, float* __restrict__ OUText, int do_relu) {
    int w = (blockIdx.x * blockDim.x + threadIdx.x) >> 5;
    int lane = threadIdx.x & 31;
    if (w >= NN) return;

    float* OUT = WRITE_ACT ? (float*)g_act : OUText;

    int beg = g_rowptr[w], end = g_rowptr[w + 1];
    float adv = g_ad[w];

    // pass 1: segment max
    float m = -1e30f;
    for (int i = beg + lane; i < end; i += 32) {
        float e = g_as[g_srcidx[i]] + adv;
        e = (e > 0.f) ? e : NEG_SLOPE * e;
        m = fmaxf(m, e);
    }
    #pragma unroll
    for (int off = 16; off; off >>= 1)
        m = fmaxf(m, __shfl_xor_sync(0xffffffffu, m, off));

    // pass 2: weights (32 at a time) + feature gather
    float acc0 = 0.f, acc1 = 0.f, denom = 0.f;
    for (int base = beg; base < end; base += 32) {
        int i = base + lane;
        float wgt = 0.f;
        int s = 0;
        if (i < end) {
            s = g_srcidx[i];
            float e = g_as[s] + adv;
            e = (e > 0.f) ? e : NEG_SLOPE * e;
            wgt = __expf(e - m);
        }
        denom += wgt;
        int cnt = end - base; if (cnt > 32) cnt = 32;
        for (int j = 0; j < cnt; ++j) {
            float wj = __shfl_sync(0xffffffffu, wgt, j);
            int   sj = __shfl_sync(0xffffffffu, s, j);
            const float* hs = g_h + (size_t)sj * 64;
            acc0 = fmaf(wj, hs[lane],      acc0);
            acc1 = fmaf(wj, hs[lane + 32], acc1);
        }
    }
    #pragma unroll
    for (int off = 16; off; off >>= 1)
        denom += __shfl_xor_sync(0xffffffffu, denom, off);

    float inv = 1.f / denom;   // self-loop guarantees non-empty segment
    float o0 = fmaf(acc0, inv, bias[lane]);
    float o1 = fmaf(acc1, inv, bias[lane + 32]);
    if (do_relu) { o0 = fmaxf(o0, 0.f); o1 = fmaxf(o1, 0.f); }
    OUT[(size_t)w * 64 + lane]      = o0;
    OUT[(size_t)w * 64 + 32 + lane] = o1;
}

// ---------------- launch ----------------
extern "C" void kernel_launch(void* const* d_in, const int* in_sizes, int n_in,
                              void* d_out, int out_size) {
    const float* x   = (const float*)d_in[0];
    const void*  ei  = d_in[1];                 // int32 or int64 — detected on device
    const float* W1  = (const float*)d_in[2];
    const float* a1s = (const float*)d_in[3];
    const float* a1d = (const float*)d_in[4];
    const float* b1  = (const float*)d_in[5];
    const float* W2  = (const float*)d_in[6];
    const float* a2s = (const float*)d_in[7];
    const float* a2d = (const float*)d_in[8];
    const float* b2  = (const float*)d_in[9];
    float* out = (float*)d_out;

    const int SCAN_BLOCKS = (NN + 511) / 512;
    const int WARP_GRID   = (NN * 32 + 255) / 256;

    // dtype detect + CSR build (dst-sorted)
    k_detect <<<1, 256>>>((const int*)ei);
    k_init   <<<(NN  + 255) / 256, 256>>>();
    k_hist   <<<(TEg + 255) / 256, 256>>>(ei);
    k_scan1  <<<SCAN_BLOCKS, 512>>>();
    k_scan2  <<<1, 128>>>(SCAN_BLOCKS);
    k_scan3  <<<(NN  + 255) / 256, 256>>>();
    k_scatter<<<(TEg + 255) / 256, 256>>>(ei);

    // layer 1
    k_gemm<128, false><<<(NN + 63) / 64, 256>>>(x, W1);
    k_proj             <<<WARP_GRID, 256>>>(a1s, a1d);
    k_agg<true>        <<<WARP_GRID, 256>>>(b1, out /*unused*/, 1);

    // layer 2
    k_gemm<64, true>   <<<(NN + 63) / 64, 256>>>(x /*unused*/, W2);
    k_proj             <<<WARP_GRID, 256>>>(a2s, a2d);
    k_agg<false>       <<<WARP_GRID, 256>>>(b2, out, 0);
}

// round 6
// speedup vs baseline: 1.2991x; 1.2991x over previous
#include <cuda_runtime.h>

#define NN 50000
#define EE 800000
#define TEg (EE + NN)          // edges + self loops
#define NEG_SLOPE 0.2f

// -------- static device scratch (no allocations allowed) --------
__device__ __align__(16) float g_h[NN * 64];     // GEMM output (h of current layer)
__device__ __align__(16) float g_act[NN * 64];   // layer-1 activated output
__device__ float g_as[NN];
__device__ float g_ad[NN];
__device__ int   g_cnt[NN];
__device__ int   g_rowptr[NN + 1];
__device__ int   g_cursor[NN];
__device__ int   g_srcidx[TEg];
__device__ int   g_bsums[128];
__device__ int   g_boff[128];
__device__ int   g_is64;           // 1 if edge_index buffer is int64, 0 if int32

// ---------------- dtype detection ----------------
// If int64: odd 32-bit words (high halves) are all 0 (indices in [0,50000)).
// If int32: odd words are node indices, overwhelmingly nonzero.
__global__ void k_detect(const int* __restrict__ ei32) {
    __shared__ int sm[256];
    int t = threadIdx.x;
    int acc = 0;
    for (int i = t; i < 32768; i += 256)
        acc |= ei32[2 * i + 1];
    sm[t] = acc;
    __syncthreads();
    for (int off = 128; off; off >>= 1) {
        if (t < off) sm[t] |= sm[t + off];
        __syncthreads();
    }
    if (t == 0) g_is64 = (sm[0] == 0) ? 1 : 0;
}

__device__ __forceinline__ int load_idx(const void* ei, long long pos) {
    if (g_is64) return (int)((const long long*)ei)[pos];
    return ((const int*)ei)[pos];
}

// ---------------- CSR build ----------------
__global__ void k_init() {
    int i = blockIdx.x * blockDim.x + threadIdx.x;
    if (i < NN) g_cnt[i] = 0;
}

__global__ void k_hist(const void* __restrict__ ei) {
    int i = blockIdx.x * blockDim.x + threadIdx.x;
    if (i >= TEg) return;
    int d = (i < EE) ? load_idx(ei, (long long)EE + i) : (i - EE);
    if (d >= 0 && d < NN) atomicAdd(&g_cnt[d], 1);
}

__global__ void k_scan1() {
    __shared__ int sm[512];
    int t = threadIdx.x;
    int i = blockIdx.x * 512 + t;
    int v = (i < NN) ? g_cnt[i] : 0;
    sm[t] = v;
    __syncthreads();
    for (int off = 1; off < 512; off <<= 1) {
        int add = (t >= off) ? sm[t - off] : 0;
        __syncthreads();
        sm[t] += add;
        __syncthreads();
    }
    if (i < NN) g_rowptr[i + 1] = sm[t];
    if (t == 511) g_bsums[blockIdx.x] = sm[511];
}

__global__ void k_scan2(int nblocks) {
    __shared__ int sm[128];
    int t = threadIdx.x;
    int v = (t < nblocks) ? g_bsums[t] : 0;
    sm[t] = v;
    __syncthreads();
    for (int off = 1; off < 128; off <<= 1) {
        int add = (t >= off) ? sm[t - off] : 0;
        __syncthreads();
        sm[t] += add;
        __syncthreads();
    }
    g_boff[t] = sm[t] - v;  // exclusive prefix of block sums
}

__global__ void k_scan3() {
    int i = blockIdx.x * blockDim.x + threadIdx.x;
    if (i == 0) { g_rowptr[0] = 0; g_cursor[0] = 0; }
    if (i < NN) {
        int v = g_rowptr[i + 1] + g_boff[i >> 9];
        g_rowptr[i + 1] = v;
        if (i + 1 < NN) g_cursor[i + 1] = v;
    }
}

__global__ void k_scatter(const void* __restrict__ ei) {
    int i = blockIdx.x * blockDim.x + threadIdx.x;
    if (i >= TEg) return;
    int s, d;
    if (i < EE) {
        s = load_idx(ei, i);
        d = load_idx(ei, (long long)EE + i);
    } else {
        s = i - EE; d = s;
    }
    if (d < 0 || d >= NN || s < 0 || s >= NN) return;
    int pos = atomicAdd(&g_cursor[d], 1);
    if (pos >= 0 && pos < TEg) g_srcidx[pos] = s;
}

// ---------------- fused GEMM + attention projections ----------------
// H[N,64] = X[N,FIN] @ W[FIN,64];  g_as[n] = H[n]·a_src;  g_ad[n] = H[n]·a_dst
// Block tile 64x64, 256 threads, thread tile 4x4, vectorized loads.
template <int FIN, bool USE_ACT>
__global__ __launch_bounds__(256)
void k_gemm(const float* __restrict__ Xext, const float* __restrict__ W,
            const float* __restrict__ a_src, const float* __restrict__ a_dst) {
    __shared__ float Xs[64][36];   // 144B rows: 16B aligned, conflict-spread
    __shared__ float Ws[32][68];

    const float* X = USE_ACT ? (const float*)g_act : Xext;

    int tid = threadIdx.x;
    int tx = tid & 15, ty = tid >> 4;
    int row0 = blockIdx.x * 64;

    float acc[4][4] = {};

    for (int k0 = 0; k0 < FIN; k0 += 32) {
        // X tile: 64 rows x 32 k = 512 float4, 2 per thread
        #pragma unroll
        for (int l = 0; l < 2; ++l) {
            int idx = l * 256 + tid;
            int r = idx >> 3, kk4 = idx & 7;
            int row = row0 + r;
            float4 v = make_float4(0.f, 0.f, 0.f, 0.f);
            if (row < NN) v = *(const float4*)(X + (size_t)row * FIN + k0 + kk4 * 4);
            *(float4*)(&Xs[r][kk4 * 4]) = v;
        }
        // W tile: 32 k x 64 cols = 512 float4, 2 per thread
        #pragma unroll
        for (int l = 0; l < 2; ++l) {
            int idx = l * 256 + tid;
            int k = idx >> 4, c4 = idx & 15;
            float4 v = *(const float4*)(W + (size_t)(k0 + k) * 64 + c4 * 4);
            *(float4*)(&Ws[k][c4 * 4]) = v;
        }
        __syncthreads();

        #pragma unroll
        for (int kk = 0; kk < 32; ++kk) {
            float4 wv = *(const float4*)(&Ws[kk][tx * 4]);
            float xv[4];
            #pragma unroll
            for (int r = 0; r < 4; ++r) xv[r] = Xs[ty * 4 + r][kk];
            #pragma unroll
            for (int r = 0; r < 4; ++r) {
                acc[r][0] = fmaf(xv[r], wv.x, acc[r][0]);
                acc[r][1] = fmaf(xv[r], wv.y, acc[r][1]);
                acc[r][2] = fmaf(xv[r], wv.z, acc[r][2]);
                acc[r][3] = fmaf(xv[r], wv.w, acc[r][3]);
            }
        }
        __syncthreads();
    }

    // epilogue: store H + per-row attention projections
    float a_s[4], a_d[4];
    #pragma unroll
    for (int c = 0; c < 4; ++c) { a_s[c] = a_src[tx * 4 + c]; a_d[c] = a_dst[tx * 4 + c]; }

    #pragma unroll
    for (int r = 0; r < 4; ++r) {
        int row = row0 + ty * 4 + r;
        float s = 0.f, d = 0.f;
        #pragma unroll
        for (int c = 0; c < 4; ++c) { s = fmaf(acc[r][c], a_s[c], s); d = fmaf(acc[r][c], a_d[c], d); }
        #pragma unroll
        for (int off = 8; off; off >>= 1) {
            s += __shfl_xor_sync(0xffffffffu, s, off, 16);
            d += __shfl_xor_sync(0xffffffffu, d, off, 16);
        }
        if (row < NN) {
            *(float4*)(g_h + (size_t)row * 64 + tx * 4) =
                make_float4(acc[r][0], acc[r][1], acc[r][2], acc[r][3]);
            if (tx == 0) { g_as[row] = s; g_ad[row] = d; }
        }
    }
}

// ---------------- single-pass online-softmax aggregation ----------------
// One warp per destination node; lane owns features {2*lane, 2*lane+1}.
template <bool WRITE_ACT>
__global__ __launch_bounds__(256)
void k_agg(const float* __restrict__ bias, float* __restrict__ OUText, int do_relu) {
    int w = (blockIdx.x * blockDim.x + threadIdx.x) >> 5;
    int lane = threadIdx.x & 31;
    if (w >= NN) return;

    float* OUT = WRITE_ACT ? (float*)g_act : OUText;

    int beg = g_rowptr[w], end = g_rowptr[w + 1];
    float adv = g_ad[w];

    float m = -1e30f;
    float acc0 = 0.f, acc1 = 0.f, denom = 0.f;

    for (int base = beg; base < end; base += 32) {
        int i = base + lane;
        float e = -1e30f;
        int s = 0;
        if (i < end) {
            s = g_srcidx[i];
            float t = g_as[s] + adv;
            e = (t > 0.f) ? t : NEG_SLOPE * t;
        }
        // batch max + rescale running state
        float bm = e;
        #pragma unroll
        for (int off = 16; off; off >>= 1)
            bm = fmaxf(bm, __shfl_xor_sync(0xffffffffu, bm, off));
        float mnew = fmaxf(m, bm);
        float scale = __expf(m - mnew);   // 0 on first batch
        acc0 *= scale; acc1 *= scale; denom *= scale;
        m = mnew;

        float wgt = (i < end) ? __expf(e - mnew) : 0.f;
        denom += wgt;

        int cnt = end - base; if (cnt > 32) cnt = 32;
        for (int j = 0; j < cnt; ++j) {
            float wj = __shfl_sync(0xffffffffu, wgt, j);
            int   sj = __shfl_sync(0xffffffffu, s, j);
            float2 v = *(const float2*)(g_h + (size_t)sj * 64 + 2 * lane);
            acc0 = fmaf(wj, v.x, acc0);
            acc1 = fmaf(wj, v.y, acc1);
        }
    }
    #pragma unroll
    for (int off = 16; off; off >>= 1)
        denom += __shfl_xor_sync(0xffffffffu, denom, off);

    float inv = 1.f / denom;   // self-loop guarantees non-empty segment
    float o0 = fmaf(acc0, inv, bias[2 * lane]);
    float o1 = fmaf(acc1, inv, bias[2 * lane + 1]);
    if (do_relu) { o0 = fmaxf(o0, 0.f); o1 = fmaxf(o1, 0.f); }
    *(float2*)(OUT + (size_t)w * 64 + 2 * lane) = make_float2(o0, o1);
}

// ---------------- launch ----------------
extern "C" void kernel_launch(void* const* d_in, const int* in_sizes, int n_in,
                              void* d_out, int out_size) {
    const float* x   = (const float*)d_in[0];
    const void*  ei  = d_in[1];                 // int32 or int64 — detected on device
    const float* W1  = (const float*)d_in[2];
    const float* a1s = (const float*)d_in[3];
    const float* a1d = (const float*)d_in[4];
    const float* b1  = (const float*)d_in[5];
    const float* W2  = (const float*)d_in[6];
    const float* a2s = (const float*)d_in[7];
    const float* a2d = (const float*)d_in[8];
    const float* b2  = (const float*)d_in[9];
    float* out = (float*)d_out;

    const int SCAN_BLOCKS = (NN + 511) / 512;
    const int WARP_GRID   = (NN * 32 + 255) / 256;

    // dtype detect + CSR build (dst-sorted)
    k_detect <<<1, 256>>>((const int*)ei);
    k_init   <<<(NN  + 255) / 256, 256>>>();
    k_hist   <<<(TEg + 255) / 256, 256>>>(ei);
    k_scan1  <<<SCAN_BLOCKS, 512>>>();
    k_scan2  <<<1, 128>>>(SCAN_BLOCKS);
    k_scan3  <<<(NN  + 255) / 256, 256>>>();
    k_scatter<<<(TEg + 255) / 256, 256>>>(ei);

    // layer 1
    k_gemm<128, false><<<(NN + 63) / 64, 256>>>(x, W1, a1s, a1d);
    k_agg<true>        <<<WARP_GRID, 256>>>(b1, out /*unused*/, 1);

    // layer 2
    k_gemm<64, true>   <<<(NN + 63) / 64, 256>>>(x /*unused*/, W2, a2s, a2d);
    k_agg<false>       <<<WARP_GRID, 256>>>(b2, out, 0);
}